// round 11
// baseline (speedup 1.0000x reference)
#include <cuda_runtime.h>
#include <cuda_bf16.h>
#include <mma.h>

using namespace nvcuda;

#define NMAX 50000
#define NPAD 50176          // padded row count: GEMM epilogue writes full 128-row tiles
#define EMAX 800000
#define DIM  128
#define NG   64

// ---------------- device scratch (static, no runtime allocation) ------------
__device__ float g_deg[NMAX];
__device__ float g_dinv[NMAX];
__device__ int   g_cnt[NMAX];
__device__ int   g_off[NMAX + 1];
__device__ int   g_cursor[NMAX];
__device__ int   g_esrc[EMAX + NMAX];
__device__ float g_enorm[EMAX + NMAX];
__device__ float g_B0[(size_t)NPAD * DIM];
__device__ float g_B1[(size_t)NPAD * DIM];
__device__ float g_pooled[NG * DIM];
__device__ int   g_gcnt[NG];

// ---------------- small init kernels ---------------------------------------
__global__ void zero_small_k() {
    int t = threadIdx.x;
    for (int i = t; i < NG * DIM; i += blockDim.x) g_pooled[i] = 0.f;
    if (t < NG) g_gcnt[t] = 0;
}

__global__ void node_init_k(const int* __restrict__ batch, int n) {
    int i = blockIdx.x * blockDim.x + threadIdx.x;
    if (i < n) {
        g_deg[i] = 1.0f;   // self-loop weight
        g_cnt[i] = 1;      // self-loop CSR slot
        atomicAdd(&g_gcnt[batch[i]], 1);
    }
}

__global__ void edge_count_k(const int* __restrict__ col,
                             const float* __restrict__ ew, int ne) {
    int e = blockIdx.x * blockDim.x + threadIdx.x;
    if (e < ne) {
        int c = col[e];
        atomicAdd(&g_deg[c], ew[e]);
        atomicAdd(&g_cnt[c], 1);
    }
}

__global__ void dinv_k(int n) {
    int i = blockIdx.x * blockDim.x + threadIdx.x;
    if (i < n) g_dinv[i] = rsqrtf(g_deg[i]);   // deg >= 1 always (self loop)
}

// single-block exclusive scan of g_cnt -> g_off (n up to 50176)
__global__ __launch_bounds__(1024) void scan_k(int n) {
    int tid = threadIdx.x;
    int chunk = (n + 1023) >> 10;
    int begin = min(tid * chunk, n);
    int end = min(begin + chunk, n);
    int s = 0;
    for (int i = begin; i < end; i++) s += g_cnt[i];

    int lane = tid & 31, wid = tid >> 5;
    int v = s;
#pragma unroll
    for (int o = 1; o < 32; o <<= 1) {
        int t = __shfl_up_sync(0xFFFFFFFFu, v, o);
        if (lane >= o) v += t;
    }
    __shared__ int ws[32];
    if (lane == 31) ws[wid] = v;
    __syncthreads();
    if (wid == 0) {
        int t2 = ws[lane];
#pragma unroll
        for (int o = 1; o < 32; o <<= 1) {
            int t = __shfl_up_sync(0xFFFFFFFFu, t2, o);
            if (lane >= o) t2 += t;
        }
        ws[lane] = t2;
    }
    __syncthreads();
    int exc = v - s + (wid ? ws[wid - 1] : 0);
    int run = exc;
    for (int i = begin; i < end; i++) { g_off[i] = run; run += g_cnt[i]; }
    if (tid == 1023) g_off[n] = run;   // last thread's run == grand total
}

__global__ void fill_self_k(int n) {
    int i = blockIdx.x * blockDim.x + threadIdx.x;
    if (i < n) {
        int s = g_off[i];
        float di = g_dinv[i];
        g_esrc[s] = i;
        g_enorm[s] = di * di;
        g_cursor[i] = s + 1;
    }
}

__global__ void fill_edges_k(const int* __restrict__ row,
                             const int* __restrict__ col,
                             const float* __restrict__ ew, int ne) {
    int e = blockIdx.x * blockDim.x + threadIdx.x;
    if (e < ne) {
        int r = row[e];
        int c = col[e];
        int pos = atomicAdd(&g_cursor[c], 1);
        g_esrc[pos] = r;
        g_enorm[pos] = g_dinv[r] * ew[e] * g_dinv[c];
    }
}

// ---------------- TF32 tensor-core GEMM: C[*,128] = A[n,128] @ B[128,128] ---
// Block tile 128x128, BK=32, 256 threads = 8 warps in 4(m) x 2(n) grid.
// Each warp: 32x64 = 2x4 wmma 16x16 tiles. A loads guarded (rows >= n -> 0,
// optional fused relu). C stored UNGUARDED: C must have >= round_up(n,128) rows.
#define A_LD 40    // 40 % 32 == 8 -> conflict-free wmma phase
#define B_LD 136   // 136 % 32 == 8

__global__ __launch_bounds__(256) void gemm_tf32_k(const float* __restrict__ A,
                                                   const float* __restrict__ B,
                                                   float* __restrict__ C,
                                                   int n, int reluIn) {
    __shared__ float As[128 * A_LD];
    __shared__ float Bs[32 * B_LD];

    int tid = threadIdx.x;
    int wid = tid >> 5;
    int warp_m = wid >> 1;      // 0..3  -> rows warp_m*32
    int warp_n = wid & 1;       // 0..1  -> cols warp_n*64
    int row0 = blockIdx.x * 128;

    wmma::fragment<wmma::accumulator, 16, 16, 8, float> acc[2][4];
#pragma unroll
    for (int i = 0; i < 2; i++)
#pragma unroll
        for (int j = 0; j < 4; j++) wmma::fill_fragment(acc[i][j], 0.f);

#pragma unroll 1
    for (int kt = 0; kt < 4; kt++) {
        int k0 = kt * 32;
        // load A tile 128x32 (4 float4 per thread)
#pragma unroll
        for (int i = 0; i < 4; i++) {
            int lin = tid + i * 256;          // 0..1023
            int r = lin >> 3;                 // 0..127
            int c4 = (lin & 7) * 4;           // 0..28
            float4 av = make_float4(0.f, 0.f, 0.f, 0.f);
            int gr = row0 + r;
            if (gr < n) av = *(const float4*)(A + (size_t)gr * DIM + k0 + c4);
            if (reluIn) {
                av.x = fmaxf(av.x, 0.f); av.y = fmaxf(av.y, 0.f);
                av.z = fmaxf(av.z, 0.f); av.w = fmaxf(av.w, 0.f);
            }
            float* dst = &As[r * A_LD + c4];
            dst[0] = av.x; dst[1] = av.y; dst[2] = av.z; dst[3] = av.w;
        }
        // load B tile 32x128 (4 float4 per thread)
#pragma unroll
        for (int i = 0; i < 4; i++) {
            int lin = tid + i * 256;
            int r = lin >> 5;                 // 0..31
            int c4 = (lin & 31) * 4;          // 0..124
            float4 bv = *(const float4*)(B + (size_t)(k0 + r) * DIM + c4);
            float* dst = &Bs[r * B_LD + c4];
            dst[0] = bv.x; dst[1] = bv.y; dst[2] = bv.z; dst[3] = bv.w;
        }
        __syncthreads();

#pragma unroll
        for (int kk = 0; kk < 4; kk++) {
            wmma::fragment<wmma::matrix_a, 16, 16, 8, wmma::precision::tf32, wmma::row_major> af[2];
            wmma::fragment<wmma::matrix_b, 16, 16, 8, wmma::precision::tf32, wmma::row_major> bf[4];
#pragma unroll
            for (int mi = 0; mi < 2; mi++) {
                wmma::load_matrix_sync(af[mi], &As[(warp_m * 32 + mi * 16) * A_LD + kk * 8], A_LD);
#pragma unroll
                for (int t = 0; t < af[mi].num_elements; t++)
                    af[mi].x[t] = wmma::__float_to_tf32(af[mi].x[t]);
            }
#pragma unroll
            for (int nj = 0; nj < 4; nj++) {
                wmma::load_matrix_sync(bf[nj], &Bs[(kk * 8) * B_LD + warp_n * 64 + nj * 16], B_LD);
#pragma unroll
                for (int t = 0; t < bf[nj].num_elements; t++)
                    bf[nj].x[t] = wmma::__float_to_tf32(bf[nj].x[t]);
            }
#pragma unroll
            for (int mi = 0; mi < 2; mi++)
#pragma unroll
                for (int nj = 0; nj < 4; nj++)
                    wmma::mma_sync(acc[mi][nj], af[mi], bf[nj], acc[mi][nj]);
        }
        __syncthreads();
    }

    // unguarded epilogue: C has NPAD >= round_up(n,128) rows
#pragma unroll
    for (int mi = 0; mi < 2; mi++) {
        int gr = row0 + warp_m * 32 + mi * 16;
#pragma unroll
        for (int nj = 0; nj < 4; nj++) {
            int gc = warp_n * 64 + nj * 16;
            wmma::store_matrix_sync(C + (size_t)gr * DIM + gc, acc[mi][nj],
                                    DIM, wmma::mem_row_major);
        }
    }
}

// ---------------- SpMM: out[c] = sum_e enorm[e]*X[esrc[e]] + bias -----------
// warp per target node, float4 per lane, 4-edge unroll for MLP.
__global__ void spmm_k(const float* __restrict__ X,
                       const float* __restrict__ bias,
                       float* __restrict__ out, int n) {
    int w = (blockIdx.x * blockDim.x + threadIdx.x) >> 5;
    int lane = threadIdx.x & 31;
    if (w >= n) return;
    int beg = g_off[w], end = g_off[w + 1];
    const float4* X4 = (const float4*)X;
    float4 acc = make_float4(0.f, 0.f, 0.f, 0.f);
    for (int e = beg; e < end; e += 4) {
#pragma unroll
        for (int j = 0; j < 4; j++) {
            int idx = e + j;
            if (idx < end) {
                int r = g_esrc[idx];
                float nv = g_enorm[idx];
                float4 v = __ldg(&X4[(size_t)r * 32 + lane]);
                acc.x = fmaf(nv, v.x, acc.x);
                acc.y = fmaf(nv, v.y, acc.y);
                acc.z = fmaf(nv, v.z, acc.z);
                acc.w = fmaf(nv, v.w, acc.w);
            }
        }
    }
    float4 b4 = ((const float4*)bias)[lane];
    acc.x += b4.x; acc.y += b4.y; acc.z += b4.z; acc.w += b4.w;
    ((float4*)out)[(size_t)w * 32 + lane] = acc;
}

// ---------------- pooling: relu + segment-sum (batch is sorted) -------------
__global__ void pool_k(const float* __restrict__ H,
                       const int* __restrict__ batch, int n) {
    int f = threadIdx.x;                 // 128 threads = features
    int n0 = blockIdx.x * 256;
    int n1 = min(n0 + 256, n);
    if (n0 >= n1) return;
    int g = batch[n0];
    float acc = 0.f;
    for (int i = n0; i < n1; i++) {
        int gi = batch[i];
        if (gi != g) {
            atomicAdd(&g_pooled[g * DIM + f], acc);
            acc = 0.f;
            g = gi;
        }
        acc += fmaxf(H[(size_t)i * DIM + f], 0.f);
    }
    atomicAdd(&g_pooled[g * DIM + f], acc);
}

// ---------------- head: out[g] = dot(pooled[g]/cnt[g], Wh) + bh -------------
__global__ void head_k(const float* __restrict__ Wh,
                       const float* __restrict__ bh,
                       float* __restrict__ out) {
    int g = blockIdx.x;
    int t = threadIdx.x;                 // 128 threads
    float c = fmaxf((float)g_gcnt[g], 1.f);
    float v = g_pooled[g * DIM + t] * Wh[t];
#pragma unroll
    for (int o = 16; o > 0; o >>= 1) v += __shfl_xor_sync(0xFFFFFFFFu, v, o);
    __shared__ float ws[4];
    if ((t & 31) == 0) ws[t >> 5] = v;
    __syncthreads();
    if (t == 0) out[g] = (ws[0] + ws[1] + ws[2] + ws[3]) / c + bh[0];
}

// ---------------- launch -----------------------------------------------------
extern "C" void kernel_launch(void* const* d_in, const int* in_sizes, int n_in,
                              void* d_out, int out_size) {
    const float* x     = (const float*)d_in[0];
    const float* ew    = (const float*)d_in[1];
    const float* W1    = (const float*)d_in[2];
    const float* b1    = (const float*)d_in[3];
    const float* W2    = (const float*)d_in[4];
    const float* b2    = (const float*)d_in[5];
    const float* Wh    = (const float*)d_in[6];
    const float* bh    = (const float*)d_in[7];
    const int*   eidx  = (const int*)d_in[8];   // int32: JAX x64 is disabled
    const int*   batch = (const int*)d_in[9];   // int32

    int E = in_sizes[8] / 2;   // edge_index is (2, E)
    int N = in_sizes[9];
    const int* row = eidx;
    const int* col = eidx + E;

    float *B0p = nullptr, *B1p = nullptr;
    cudaGetSymbolAddress((void**)&B0p, g_B0);
    cudaGetSymbolAddress((void**)&B1p, g_B1);

    int nbN = (N + 255) / 256;
    int nbE = (E + 255) / 256;
    int nbG = (N + 127) / 128;            // gemm blocks
    int nbS = (N * 32 + 255) / 256;       // spmm blocks (warp/node)
    int nbP = (N + 255) / 256;            // pool blocks (256 nodes/block)

    zero_small_k<<<1, 256>>>();
    node_init_k<<<nbN, 256>>>(batch, N);
    edge_count_k<<<nbE, 256>>>(col, ew, E);
    dinv_k<<<nbN, 256>>>(N);
    scan_k<<<1, 1024>>>(N);
    fill_self_k<<<nbN, 256>>>(N);
    fill_edges_k<<<nbE, 256>>>(row, col, ew, E);

    // layer 1: B0 = x @ W1 ; B1 = A_norm @ B0 + b1   (relu deferred)
    gemm_tf32_k<<<nbG, 256>>>(x, W1, B0p, N, 0);
    spmm_k<<<nbS, 256>>>(B0p, b1, B1p, N);

    // layer 2: B0 = relu(B1) @ W2 ; B1 = A_norm @ B0 + b2  (relu deferred)
    gemm_tf32_k<<<nbG, 256>>>(B1p, W2, B0p, N, 1);
    spmm_k<<<nbS, 256>>>(B0p, b2, B1p, N);

    // pooling (applies relu) + head
    pool_k<<<nbP, 128>>>(B1p, batch, N);
    head_k<<<out_size, 128>>>(Wh, bh, (float*)d_out);
}

// round 14
// speedup vs baseline: 1.6127x; 1.6127x over previous
#include <cuda_runtime.h>
#include <cuda_bf16.h>

#define NMAX 50000
#define NPAD 50176          // padded row count: GEMM epilogue writes full 128-row tiles
#define EMAX 800000
#define DIM  128
#define NG   64

// ---------------- device scratch (static, no runtime allocation) ------------
__device__ float g_deg[NMAX];
__device__ float g_dinv[NMAX];
__device__ int   g_cnt[NMAX];
__device__ int   g_off[NMAX + 1];
__device__ int   g_cursor[NMAX];
__device__ int   g_esrc[EMAX + NMAX];
__device__ float g_enorm[EMAX + NMAX];
__device__ float g_B0[(size_t)NPAD * DIM];
__device__ float g_B1[(size_t)NPAD * DIM];
__device__ float g_pooled[NG * DIM];
__device__ int   g_gcnt[NG];

// round-to-nearest fp32 -> tf32 (matches wmma::__float_to_tf32)
__device__ __forceinline__ float to_tf32_rna(float x) {
    unsigned u;
    asm("cvt.rna.tf32.f32 %0, %1;" : "=r"(u) : "f"(x));
    return __uint_as_float(u);
}

// ---------------- small init kernels ---------------------------------------
__global__ void zero_small_k() {
    int t = threadIdx.x;
    for (int i = t; i < NG * DIM; i += blockDim.x) g_pooled[i] = 0.f;
    if (t < NG) g_gcnt[t] = 0;
}

__global__ void node_init_k(const int* __restrict__ batch, int n) {
    int i = blockIdx.x * blockDim.x + threadIdx.x;
    if (i < n) {
        g_deg[i] = 1.0f;   // self-loop weight
        g_cnt[i] = 1;      // self-loop CSR slot
        atomicAdd(&g_gcnt[batch[i]], 1);
    }
}

__global__ void edge_count_k(const int* __restrict__ col,
                             const float* __restrict__ ew, int ne) {
    int e = blockIdx.x * blockDim.x + threadIdx.x;
    if (e < ne) {
        int c = col[e];
        atomicAdd(&g_deg[c], ew[e]);
        atomicAdd(&g_cnt[c], 1);
    }
}

__global__ void dinv_k(int n) {
    int i = blockIdx.x * blockDim.x + threadIdx.x;
    if (i < n) g_dinv[i] = rsqrtf(g_deg[i]);   // deg >= 1 always (self loop)
}

// single-block exclusive scan of g_cnt -> g_off (n up to 50176)
__global__ __launch_bounds__(1024) void scan_k(int n) {
    int tid = threadIdx.x;
    int chunk = (n + 1023) >> 10;
    int begin = min(tid * chunk, n);
    int end = min(begin + chunk, n);
    int s = 0;
    for (int i = begin; i < end; i++) s += g_cnt[i];

    int lane = tid & 31, wid = tid >> 5;
    int v = s;
#pragma unroll
    for (int o = 1; o < 32; o <<= 1) {
        int t = __shfl_up_sync(0xFFFFFFFFu, v, o);
        if (lane >= o) v += t;
    }
    __shared__ int ws[32];
    if (lane == 31) ws[wid] = v;
    __syncthreads();
    if (wid == 0) {
        int t2 = ws[lane];
#pragma unroll
        for (int o = 1; o < 32; o <<= 1) {
            int t = __shfl_up_sync(0xFFFFFFFFu, t2, o);
            if (lane >= o) t2 += t;
        }
        ws[lane] = t2;
    }
    __syncthreads();
    int exc = v - s + (wid ? ws[wid - 1] : 0);
    int run = exc;
    for (int i = begin; i < end; i++) { g_off[i] = run; run += g_cnt[i]; }
    if (tid == 1023) g_off[n] = run;   // last thread's run == grand total
}

__global__ void fill_self_k(int n) {
    int i = blockIdx.x * blockDim.x + threadIdx.x;
    if (i < n) {
        int s = g_off[i];
        float di = g_dinv[i];
        g_esrc[s] = i;
        g_enorm[s] = di * di;
        g_cursor[i] = s + 1;
    }
}

__global__ void fill_edges_k(const int* __restrict__ row,
                             const int* __restrict__ col,
                             const float* __restrict__ ew, int ne) {
    int e = blockIdx.x * blockDim.x + threadIdx.x;
    if (e < ne) {
        int r = row[e];
        int c = col[e];
        int pos = atomicAdd(&g_cursor[c], 1);
        g_esrc[pos] = r;
        g_enorm[pos] = g_dinv[r] * ew[e] * g_dinv[c];
    }
}

// ---------------- TF32 PTX-mma GEMM: C[*,128] = A[n,128] @ B[128,128] -------
// 128x128 CTA tile, BK=32, 256 threads = 8 warps (4m x 2n), warp tile 32x64.
// mma.sync.aligned.m16n8k8 tf32, manual conflict-free fragment loads.
// Staged values are converted fp32->tf32 with round-to-nearest (cvt.rna) —
// raw-bit truncation is biased and fails the 1e-3 tolerance after 2 layers.
// A loads guarded (rows >= n -> 0, optional fused relu); epilogue unguarded
// (C must have >= round_up(n,128) rows — scratch is NPAD).
#define A_LD 36    // bank(addr) = (4r + c) % 32 -> A frag (8r x 4c) conflict-free
#define B_LD 136   // bank(addr) = (8k + n) % 32 -> B frag (4k x 8n) conflict-free

__global__ __launch_bounds__(256) void gemm_mma_k(const float* __restrict__ A,
                                                  const float* __restrict__ B,
                                                  float* __restrict__ C,
                                                  int n, int reluIn) {
    __shared__ float As[128 * A_LD];   // [row][k], k = 0..31
    __shared__ float Bs[32 * B_LD];    // [k][n],   n = 0..127

    int tid = threadIdx.x;
    int wid = tid >> 5;
    int lane = tid & 31;
    int warp_m = wid >> 1;                 // 0..3 -> rows warp_m*32
    int warp_n = wid & 1;                  // 0..1 -> cols warp_n*64
    int row0 = blockIdx.x * 128;

    int qr = lane >> 2;                    // 0..7  (quad row)
    int qc = lane & 3;                     // 0..3  (quad col)

    float acc[2][8][4];
#pragma unroll
    for (int mi = 0; mi < 2; mi++)
#pragma unroll
        for (int j = 0; j < 8; j++)
#pragma unroll
            for (int t = 0; t < 4; t++) acc[mi][j][t] = 0.f;

#pragma unroll 1
    for (int kt = 0; kt < 4; kt++) {
        int k0 = kt * 32;
        // ---- stage A tile: 128 rows x 32 k (4 float4 per thread) ----
#pragma unroll
        for (int i = 0; i < 4; i++) {
            int lin = tid + i * 256;          // 0..1023
            int r = lin >> 3;                 // 0..127
            int c4 = (lin & 7) * 4;           // 0,4,...,28
            float4 av = make_float4(0.f, 0.f, 0.f, 0.f);
            int gr = row0 + r;
            if (gr < n) av = *(const float4*)(A + (size_t)gr * DIM + k0 + c4);
            if (reluIn) {
                av.x = fmaxf(av.x, 0.f); av.y = fmaxf(av.y, 0.f);
                av.z = fmaxf(av.z, 0.f); av.w = fmaxf(av.w, 0.f);
            }
            float* dst = &As[r * A_LD + c4];
            dst[0] = to_tf32_rna(av.x); dst[1] = to_tf32_rna(av.y);
            dst[2] = to_tf32_rna(av.z); dst[3] = to_tf32_rna(av.w);
        }
        // ---- stage B tile: 32 k x 128 n (4 float4 per thread) ----
#pragma unroll
        for (int i = 0; i < 4; i++) {
            int lin = tid + i * 256;
            int r = lin >> 5;                 // 0..31
            int c4 = (lin & 31) * 4;          // 0..124
            float4 bv = *(const float4*)(B + (size_t)(k0 + r) * DIM + c4);
            float* dst = &Bs[r * B_LD + c4];
            dst[0] = to_tf32_rna(bv.x); dst[1] = to_tf32_rna(bv.y);
            dst[2] = to_tf32_rna(bv.z); dst[3] = to_tf32_rna(bv.w);
        }
        __syncthreads();

#pragma unroll
        for (int kk = 0; kk < 4; kk++) {
            int kb = kk * 8;
            // A fragments: 2 m-tiles of m16k8
            unsigned a[2][4];
#pragma unroll
            for (int mi = 0; mi < 2; mi++) {
                int ar = warp_m * 32 + mi * 16 + qr;
                int ac = kb + qc;
                a[mi][0] = __float_as_uint(As[ar * A_LD + ac]);
                a[mi][1] = __float_as_uint(As[(ar + 8) * A_LD + ac]);
                a[mi][2] = __float_as_uint(As[ar * A_LD + ac + 4]);
                a[mi][3] = __float_as_uint(As[(ar + 8) * A_LD + ac + 4]);
            }
            // B fragments: 8 n-tiles of k8n8 (col-major fragment map)
            unsigned b[8][2];
#pragma unroll
            for (int j = 0; j < 8; j++) {
                int bk = kb + qc;
                int bn = warp_n * 64 + j * 8 + qr;
                b[j][0] = __float_as_uint(Bs[bk * B_LD + bn]);
                b[j][1] = __float_as_uint(Bs[(bk + 4) * B_LD + bn]);
            }
#pragma unroll
            for (int mi = 0; mi < 2; mi++)
#pragma unroll
                for (int j = 0; j < 8; j++) {
                    asm volatile(
                        "mma.sync.aligned.m16n8k8.row.col.f32.tf32.tf32.f32 "
                        "{%0,%1,%2,%3}, {%4,%5,%6,%7}, {%8,%9}, {%0,%1,%2,%3};"
                        : "+f"(acc[mi][j][0]), "+f"(acc[mi][j][1]),
                          "+f"(acc[mi][j][2]), "+f"(acc[mi][j][3])
                        : "r"(a[mi][0]), "r"(a[mi][1]), "r"(a[mi][2]), "r"(a[mi][3]),
                          "r"(b[j][0]), "r"(b[j][1]));
                }
        }
        __syncthreads();
    }

    // ---- epilogue (unguarded; C has NPAD >= round_up(n,128) rows) ----
    // c0,c1 at (row qr, cols 2*qc, 2*qc+1); c2,c3 at (row qr+8, same cols)
#pragma unroll
    for (int mi = 0; mi < 2; mi++) {
        int r1 = row0 + warp_m * 32 + mi * 16 + qr;
        int r2 = r1 + 8;
#pragma unroll
        for (int j = 0; j < 8; j++) {
            int cc = warp_n * 64 + j * 8 + qc * 2;
            *(float2*)(C + (size_t)r1 * DIM + cc) = make_float2(acc[mi][j][0], acc[mi][j][1]);
            *(float2*)(C + (size_t)r2 * DIM + cc) = make_float2(acc[mi][j][2], acc[mi][j][3]);
        }
    }
}

// ---------------- SpMM: out[c] = sum_e enorm[e]*X[esrc[e]] + bias -----------
// warp per target node, float4 per lane, 4-edge unroll for MLP.
__global__ void spmm_k(const float* __restrict__ X,
                       const float* __restrict__ bias,
                       float* __restrict__ out, int n) {
    int w = (blockIdx.x * blockDim.x + threadIdx.x) >> 5;
    int lane = threadIdx.x & 31;
    if (w >= n) return;
    int beg = g_off[w], end = g_off[w + 1];
    const float4* X4 = (const float4*)X;
    float4 acc = make_float4(0.f, 0.f, 0.f, 0.f);
    for (int e = beg; e < end; e += 4) {
#pragma unroll
        for (int j = 0; j < 4; j++) {
            int idx = e + j;
            if (idx < end) {
                int r = g_esrc[idx];
                float nv = g_enorm[idx];
                float4 v = __ldg(&X4[(size_t)r * 32 + lane]);
                acc.x = fmaf(nv, v.x, acc.x);
                acc.y = fmaf(nv, v.y, acc.y);
                acc.z = fmaf(nv, v.z, acc.z);
                acc.w = fmaf(nv, v.w, acc.w);
            }
        }
    }
    float4 b4 = ((const float4*)bias)[lane];
    acc.x += b4.x; acc.y += b4.y; acc.z += b4.z; acc.w += b4.w;
    ((float4*)out)[(size_t)w * 32 + lane] = acc;
}

// ---------------- pooling: relu + segment-sum (batch is sorted) -------------
__global__ void pool_k(const float* __restrict__ H,
                       const int* __restrict__ batch, int n) {
    int f = threadIdx.x;                 // 128 threads = features
    int n0 = blockIdx.x * 256;
    int n1 = min(n0 + 256, n);
    if (n0 >= n1) return;
    int g = batch[n0];
    float acc = 0.f;
    for (int i = n0; i < n1; i++) {
        int gi = batch[i];
        if (gi != g) {
            atomicAdd(&g_pooled[g * DIM + f], acc);
            acc = 0.f;
            g = gi;
        }
        acc += fmaxf(H[(size_t)i * DIM + f], 0.f);
    }
    atomicAdd(&g_pooled[g * DIM + f], acc);
}

// ---------------- head: out[g] = dot(pooled[g]/cnt[g], Wh) + bh -------------
__global__ void head_k(const float* __restrict__ Wh,
                       const float* __restrict__ bh,
                       float* __restrict__ out) {
    int g = blockIdx.x;
    int t = threadIdx.x;                 // 128 threads
    float c = fmaxf((float)g_gcnt[g], 1.f);
    float v = g_pooled[g * DIM + t] * Wh[t];
#pragma unroll
    for (int o = 16; o > 0; o >>= 1) v += __shfl_xor_sync(0xFFFFFFFFu, v, o);
    __shared__ float ws[4];
    if ((t & 31) == 0) ws[t >> 5] = v;
    __syncthreads();
    if (t == 0) out[g] = (ws[0] + ws[1] + ws[2] + ws[3]) / c + bh[0];
}

// ---------------- launch -----------------------------------------------------
extern "C" void kernel_launch(void* const* d_in, const int* in_sizes, int n_in,
                              void* d_out, int out_size) {
    const float* x     = (const float*)d_in[0];
    const float* ew    = (const float*)d_in[1];
    const float* W1    = (const float*)d_in[2];
    const float* b1    = (const float*)d_in[3];
    const float* W2    = (const float*)d_in[4];
    const float* b2    = (const float*)d_in[5];
    const float* Wh    = (const float*)d_in[6];
    const float* bh    = (const float*)d_in[7];
    const int*   eidx  = (const int*)d_in[8];   // int32: JAX x64 is disabled
    const int*   batch = (const int*)d_in[9];   // int32

    int E = in_sizes[8] / 2;   // edge_index is (2, E)
    int N = in_sizes[9];
    const int* row = eidx;
    const int* col = eidx + E;

    float *B0p = nullptr, *B1p = nullptr;
    cudaGetSymbolAddress((void**)&B0p, g_B0);
    cudaGetSymbolAddress((void**)&B1p, g_B1);

    int nbN = (N + 255) / 256;
    int nbE = (E + 255) / 256;
    int nbG = (N + 127) / 128;            // gemm blocks
    int nbS = (N * 32 + 255) / 256;       // spmm blocks (warp/node)
    int nbP = (N + 255) / 256;            // pool blocks (256 nodes/block)

    zero_small_k<<<1, 256>>>();
    node_init_k<<<nbN, 256>>>(batch, N);
    edge_count_k<<<nbE, 256>>>(col, ew, E);
    dinv_k<<<nbN, 256>>>(N);
    scan_k<<<1, 1024>>>(N);
    fill_self_k<<<nbN, 256>>>(N);
    fill_edges_k<<<nbE, 256>>>(row, col, ew, E);

    // layer 1: B0 = x @ W1 ; B1 = A_norm @ B0 + b1   (relu deferred)
    gemm_mma_k<<<nbG, 256>>>(x, W1, B0p, N, 0);
    spmm_k<<<nbS, 256>>>(B0p, b1, B1p, N);

    // layer 2: B0 = relu(B1) @ W2 ; B1 = A_norm @ B0 + b2  (relu deferred)
    gemm_mma_k<<<nbG, 256>>>(B1p, W2, B0p, N, 1);
    spmm_k<<<nbS, 256>>>(B0p, b2, B1p, N);

    // pooling (applies relu) + head
    pool_k<<<nbP, 128>>>(B1p, batch, N);
    head_k<<<out_size, 128>>>(Wh, bh, (float*)d_out);
}